// round 9
// baseline (speedup 1.0000x reference)
#include <cuda_runtime.h>
#include <cstdint>

// Problem constants: x is [64,3,224,224] f32, out is [16,64,3,224,224] f32.
#define NELEM    9633792      // 64*3*224*224
#define HWPLANE  50176        // 224*224
#define IMGSIZE  150528       // 3*224*224
#define TSTEPS   16
#define EPT      4            // elements per thread per iteration (float4)
#define BLOCKS   588          // 588*256*4 = 602112 = 4 images exactly
#define NITER    16           // 602112 * 16 = NELEM exactly
#define STRIDE   602112u      // elements advanced per iteration

// ---------------------------------------------------------------------------
// Compile-time key schedule: keys[t] = threefry2x32((0,1), (0,t)) under the
// partitionable split, with the 6 key-injection constants pre-folded.
// ---------------------------------------------------------------------------
struct Keys { unsigned a0,b0,a1,b1,a2,b2,a3,b3,a4,b4,a5,b5; };

__host__ __device__ constexpr unsigned rotlc(unsigned v, int r) {
    return (v << r) | (v >> (32 - r));
}

__host__ __device__ constexpr Keys make_keys(int t) {
    const unsigned k0 = 0u, k1 = 1u;
    const unsigned k2 = k0 ^ k1 ^ 0x1BD11BDAu;
    unsigned x0 = k0;                 // c0 = 0
    unsigned x1 = (unsigned)t + k1;   // c1 = t
    x0+=x1; x1=rotlc(x1,13); x1^=x0;
    x0+=x1; x1=rotlc(x1,15); x1^=x0;
    x0+=x1; x1=rotlc(x1,26); x1^=x0;
    x0+=x1; x1=rotlc(x1, 6); x1^=x0;
    x0+=k1; x1+=k2+1u;
    x0+=x1; x1=rotlc(x1,17); x1^=x0;
    x0+=x1; x1=rotlc(x1,29); x1^=x0;
    x0+=x1; x1=rotlc(x1,16); x1^=x0;
    x0+=x1; x1=rotlc(x1,24); x1^=x0;
    x0+=k2; x1+=k0+2u;
    x0+=x1; x1=rotlc(x1,13); x1^=x0;
    x0+=x1; x1=rotlc(x1,15); x1^=x0;
    x0+=x1; x1=rotlc(x1,26); x1^=x0;
    x0+=x1; x1=rotlc(x1, 6); x1^=x0;
    x0+=k0; x1+=k1+3u;
    x0+=x1; x1=rotlc(x1,17); x1^=x0;
    x0+=x1; x1=rotlc(x1,29); x1^=x0;
    x0+=x1; x1=rotlc(x1,16); x1^=x0;
    x0+=x1; x1=rotlc(x1,24); x1^=x0;
    x0+=k1; x1+=k2+4u;
    x0+=x1; x1=rotlc(x1,13); x1^=x0;
    x0+=x1; x1=rotlc(x1,15); x1^=x0;
    x0+=x1; x1=rotlc(x1,26); x1^=x0;
    x0+=x1; x1=rotlc(x1, 6); x1^=x0;
    x0+=k2; x1+=k0+5u;
    const unsigned K0 = x0, K1 = x1, K2 = K0 ^ K1 ^ 0x1BD11BDAu;
    return Keys{K0,K1, K1,K2+1u, K2,K0+2u, K0,K1+3u, K1,K2+4u, K2,K0+5u};
}

// ---------------------------------------------------------------------------
// FMA-pipe integer adds. 'one' (==1) comes from a kernel parameter, so ptxas
// cannot strength-reduce the IMAD forms back to IADD3.
// ---------------------------------------------------------------------------
__device__ __forceinline__ unsigned addf(unsigned a, unsigned b, unsigned one) {
    unsigned d;
    asm("mad.lo.u32 %0, %1, %2, %3;" : "=r"(d) : "r"(a), "r"(one), "r"(b));
    return d;
}

template<unsigned IMM>
__device__ __forceinline__ unsigned addimm(unsigned x, unsigned one) {
    unsigned d;
    asm("mad.lo.u32 %0, %1, %2, %3;" : "=r"(d) : "r"(one), "n"(IMM), "r"(x));
    return d;
}

// (bits >> 9) | 0x3f800000 as one op: hi32(bits * 2^23) + 0x3f800000
// (disjoint bit ranges, so OR == ADD). fma pipe (has headroom).
__device__ __forceinline__ unsigned ubits(unsigned bits, unsigned c23) {
    unsigned d;
    asm("mad.hi.u32 %0, %1, %2, %3;" : "=r"(d) : "r"(bits), "r"(c23),
        "n"(0x3f800000));
    return d;
}

// ---------------------------------------------------------------------------
// threefry2x32 (JAX-exact 20 rounds) with all key material as immediates.
// Returns o0 ^ o1 (partitionable bits fold).
// ---------------------------------------------------------------------------
template<unsigned A0,unsigned B0,unsigned A1,unsigned B1,unsigned A2,unsigned B2,
         unsigned A3,unsigned B3,unsigned A4,unsigned B4,unsigned A5,unsigned B5>
__device__ __forceinline__ unsigned tf_bits(unsigned c1, unsigned one) {
    unsigned x1 = addimm<B0>(c1, one);
    unsigned x0 = addimm<A0>(x1, one);   // round-1 add folded with x0 init
    x1 = __funnelshift_l(x1, x1, 13); x1 ^= x0;
#define TFR(r) { x0 = addf(x1, x0, one); \
                 x1 = __funnelshift_l(x1, x1, (r)); x1 ^= x0; }
    TFR(15) TFR(26) TFR(6)
    x0 = addimm<A1>(x0, one); x1 = addimm<B1>(x1, one);
    TFR(17) TFR(29) TFR(16) TFR(24)
    x0 = addimm<A2>(x0, one); x1 = addimm<B2>(x1, one);
    TFR(13) TFR(15) TFR(26) TFR(6)
    x0 = addimm<A3>(x0, one); x1 = addimm<B3>(x1, one);
    TFR(17) TFR(29) TFR(16) TFR(24)
    x0 = addimm<A4>(x0, one); x1 = addimm<B4>(x1, one);
    TFR(13) TFR(15) TFR(26) TFR(6)
    x0 = addimm<A5>(x0, one); x1 = addimm<B5>(x1, one);
#undef TFR
    return x0 ^ x1;
}

// ---------------------------------------------------------------------------
// Predicated Bernoulli tail (one clamp per path; invariants make the other a
// no-op). Equivalent to: sp=u<p; oval=sp?ov1:ov0; rem=min(max(rem-sp,0),SM1).
// ---------------------------------------------------------------------------
__device__ __forceinline__ float bern_tail(float& rem, float u, float p,
                                           float ov0, float ov1, float sm1) {
    float oval;
    asm("{\n\t"
        ".reg .pred sp;\n\t"
        "setp.lt.f32 sp, %2, %3;\n\t"
        "selp.f32 %0, %4, %5, sp;\n\t"
        "@sp  add.f32 %1, %1, 0fBF800000;\n\t"   // rem -= 1
        "@sp  max.f32 %1, %1, 0f00000000;\n\t"   // clip low
        "@!sp min.f32 %1, %1, %6;\n\t"           // clip high
        "}"
        : "=f"(oval), "+f"(rem)
        : "f"(u), "f"(p), "f"(ov1), "f"(ov0), "f"(sm1));
    return oval;
}

// ---------------------------------------------------------------------------
// One fully specialized time step for 4 elements.
// ---------------------------------------------------------------------------
template<int T>
__device__ __forceinline__ void do_step(float rem[EPT], unsigned j,
                                        float ov0, float ov1,
                                        unsigned one, unsigned c23,
                                        float* __restrict__ out)
{
    constexpr int   S    = TSTEPS - T;            // remaining slots
    constexpr float SF   = (float)S;
    constexpr float INV  = 1.0f / SF;             // rn(1/S), exact for pow2
    constexpr float SM1  = SF - 1.0f;
    constexpr bool  POW2 = (S & (S - 1)) == 0;
    constexpr Keys  K    = make_keys(T);

    unsigned bits[EPT];
#pragma unroll
    for (int e = 0; e < EPT; e++) {
        bits[e] = tf_bits<K.a0,K.b0,K.a1,K.b1,K.a2,K.b2,
                          K.a3,K.b3,K.a4,K.b4,K.a5,K.b5>(j + (unsigned)e, one);
    }

    float ovals[EPT];
#pragma unroll
    for (int e = 0; e < EPT; e++) {
        // u = bitcast((bits>>9)|0x3f800000) - 1.0 (exact Sterbenz subtraction)
        const float u = __uint_as_float(ubits(bits[e], c23)) - 1.0f;

        // p = rn(rem/S). Reference's clip(p,0,1) is a no-op (rem in [0,S]).
        float p;
        if (S == 1) {
            p = rem[e];
        } else if (POW2) {
            p = __fmul_rn(rem[e], INV);
        } else {
            const float q0 = __fmul_rn(rem[e], INV);
            const float r  = __fmaf_rn(-SF, q0, rem[e]);
            p = __fmaf_rn(r, INV, q0);            // Markstein, correctly rounded
        }

        if (S > 1) {
            ovals[e] = bern_tail(rem[e], u, p, ov0, ov1, SM1);
        } else {
            ovals[e] = (u < p) ? ov1 : ov0;       // last step: rem is dead
        }
    }

    float4 o;
    o.x = ovals[0]; o.y = ovals[1]; o.z = ovals[2]; o.w = ovals[3];
    // Streaming store: output is write-once, never re-read.
    __stcs(reinterpret_cast<float4*>(out + (size_t)T * NELEM + j), o);
}

// ---------------------------------------------------------------------------
// Persistent single-wave kernel: 588 CTAs x 256 threads, each thread loops
// over 16 positions strided by 602112 elements = exactly 4 images. Because
// the stride is a whole number of images, (j mod IMGSIZE) — and therefore
// the channel and its m/s/ov0/ov1 — is loop-invariant per thread.
// ---------------------------------------------------------------------------
__global__ void __launch_bounds__(256, 4)
hyper_kernel(const float* __restrict__ x,
             const float* __restrict__ meanv,
             const float* __restrict__ stdv,
             float* __restrict__ out,
             unsigned one, unsigned c23)
{
    unsigned j = (blockIdx.x * blockDim.x + threadIdx.x) * EPT;  // < STRIDE

    // Loop-invariant channel constants (prologue runs once per thread).
    const unsigned c = (j / HWPLANE) % 3u;
    const float m = meanv[c];
    const float s = stdv[c];
    const float ov0 = __fdiv_rn(0.0f - m, s);   // (0 - mean)/std, IEEE
    const float ov1 = __fdiv_rn(1.0f - m, s);   // (1 - mean)/std, IEEE

#pragma unroll 1
    for (int it = 0; it < NITER; it++) {
        const float4 xv = *reinterpret_cast<const float4*>(x + j);

        // probs = clip(x*s + m, 0, 1) (separate rn mul + rn add, per XLA);
        // rem0 = probs * 16 (exact).
        float rem[EPT];
        {
            const float xs[EPT] = {xv.x, xv.y, xv.z, xv.w};
#pragma unroll
            for (int e = 0; e < EPT; e++) {
                float pr = __fadd_rn(__fmul_rn(xs[e], s), m);
                pr = fminf(fmaxf(pr, 0.0f), 1.0f);
                rem[e] = __fmul_rn(pr, 16.0f);
            }
        }

        do_step< 0>(rem, j, ov0, ov1, one, c23, out);
        do_step< 1>(rem, j, ov0, ov1, one, c23, out);
        do_step< 2>(rem, j, ov0, ov1, one, c23, out);
        do_step< 3>(rem, j, ov0, ov1, one, c23, out);
        do_step< 4>(rem, j, ov0, ov1, one, c23, out);
        do_step< 5>(rem, j, ov0, ov1, one, c23, out);
        do_step< 6>(rem, j, ov0, ov1, one, c23, out);
        do_step< 7>(rem, j, ov0, ov1, one, c23, out);
        do_step< 8>(rem, j, ov0, ov1, one, c23, out);
        do_step< 9>(rem, j, ov0, ov1, one, c23, out);
        do_step<10>(rem, j, ov0, ov1, one, c23, out);
        do_step<11>(rem, j, ov0, ov1, one, c23, out);
        do_step<12>(rem, j, ov0, ov1, one, c23, out);
        do_step<13>(rem, j, ov0, ov1, one, c23, out);
        do_step<14>(rem, j, ov0, ov1, one, c23, out);
        do_step<15>(rem, j, ov0, ov1, one, c23, out);

        j += STRIDE;
    }
}

// ---------------------------------------------------------------------------
// Launch: single kernel, graph-capturable, allocation-free. The opaque
// 'one'/'c23' params keep the IMAD forms alive through ptxas.
// ---------------------------------------------------------------------------
extern "C" void kernel_launch(void* const* d_in, const int* in_sizes, int n_in,
                              void* d_out, int out_size) {
    (void)in_sizes; (void)n_in; (void)out_size;

    const float* x  = (const float*)d_in[0];
    const float* mn = (const float*)d_in[1];
    const float* sd = (const float*)d_in[2];
    float* out = (float*)d_out;

    hyper_kernel<<<BLOCKS, 256>>>(x, mn, sd, out, 1u, 1u << 23);
}

// round 10
// speedup vs baseline: 1.2700x; 1.2700x over previous
#include <cuda_runtime.h>
#include <cstdint>

// Problem constants: x is [64,3,224,224] f32, out is [16,64,3,224,224] f32.
#define NELEM    9633792      // 64*3*224*224
#define HWPLANE  50176        // 224*224
#define TSTEPS   16
#define EPT      4            // elements per thread (float4 granularity)

// ---------------------------------------------------------------------------
// Compile-time key schedule: keys[t] = threefry2x32((0,1), (0,t)) under the
// partitionable split, with the 6 key-injection constants pre-folded.
// ---------------------------------------------------------------------------
struct Keys { unsigned a0,b0,a1,b1,a2,b2,a3,b3,a4,b4,a5,b5; };

__host__ __device__ constexpr unsigned rotlc(unsigned v, int r) {
    return (v << r) | (v >> (32 - r));
}

__host__ __device__ constexpr Keys make_keys(int t) {
    const unsigned k0 = 0u, k1 = 1u;
    const unsigned k2 = k0 ^ k1 ^ 0x1BD11BDAu;
    unsigned x0 = k0;                 // c0 = 0
    unsigned x1 = (unsigned)t + k1;   // c1 = t
    x0+=x1; x1=rotlc(x1,13); x1^=x0;
    x0+=x1; x1=rotlc(x1,15); x1^=x0;
    x0+=x1; x1=rotlc(x1,26); x1^=x0;
    x0+=x1; x1=rotlc(x1, 6); x1^=x0;
    x0+=k1; x1+=k2+1u;
    x0+=x1; x1=rotlc(x1,17); x1^=x0;
    x0+=x1; x1=rotlc(x1,29); x1^=x0;
    x0+=x1; x1=rotlc(x1,16); x1^=x0;
    x0+=x1; x1=rotlc(x1,24); x1^=x0;
    x0+=k2; x1+=k0+2u;
    x0+=x1; x1=rotlc(x1,13); x1^=x0;
    x0+=x1; x1=rotlc(x1,15); x1^=x0;
    x0+=x1; x1=rotlc(x1,26); x1^=x0;
    x0+=x1; x1=rotlc(x1, 6); x1^=x0;
    x0+=k0; x1+=k1+3u;
    x0+=x1; x1=rotlc(x1,17); x1^=x0;
    x0+=x1; x1=rotlc(x1,29); x1^=x0;
    x0+=x1; x1=rotlc(x1,16); x1^=x0;
    x0+=x1; x1=rotlc(x1,24); x1^=x0;
    x0+=k1; x1+=k2+4u;
    x0+=x1; x1=rotlc(x1,13); x1^=x0;
    x0+=x1; x1=rotlc(x1,15); x1^=x0;
    x0+=x1; x1=rotlc(x1,26); x1^=x0;
    x0+=x1; x1=rotlc(x1, 6); x1^=x0;
    x0+=k2; x1+=k0+5u;
    const unsigned K0 = x0, K1 = x1, K2 = K0 ^ K1 ^ 0x1BD11BDAu;
    return Keys{K0,K1, K1,K2+1u, K2,K0+2u, K0,K1+3u, K1,K2+4u, K2,K0+5u};
}

// ---------------------------------------------------------------------------
// FMA-pipe integer adds. 'one' (==1) comes from a kernel parameter, so ptxas
// cannot strength-reduce the IMAD forms back to IADD3.
// ---------------------------------------------------------------------------
__device__ __forceinline__ unsigned addf(unsigned a, unsigned b, unsigned one) {
    unsigned d;
    asm("mad.lo.u32 %0, %1, %2, %3;" : "=r"(d) : "r"(a), "r"(one), "r"(b));
    return d;
}

template<unsigned IMM>
__device__ __forceinline__ unsigned addimm(unsigned x, unsigned one) {
    unsigned d;
    asm("mad.lo.u32 %0, %1, %2, %3;" : "=r"(d) : "r"(one), "n"(IMM), "r"(x));
    return d;
}

// (bits >> 9) | 0x3f800000 as one op: hi32(bits * 2^23) + 0x3f800000
// (disjoint bit ranges, so OR == ADD). fma pipe (has headroom).
__device__ __forceinline__ unsigned ubits(unsigned bits, unsigned c23) {
    unsigned d;
    asm("mad.hi.u32 %0, %1, %2, %3;" : "=r"(d) : "r"(bits), "r"(c23),
        "n"(0x3f800000));
    return d;
}

// ---------------------------------------------------------------------------
// threefry2x32 (JAX-exact 20 rounds) with all key material as immediates.
// Returns o0 ^ o1 (partitionable bits fold).
// ---------------------------------------------------------------------------
template<unsigned A0,unsigned B0,unsigned A1,unsigned B1,unsigned A2,unsigned B2,
         unsigned A3,unsigned B3,unsigned A4,unsigned B4,unsigned A5,unsigned B5>
__device__ __forceinline__ unsigned tf_bits(unsigned c1, unsigned one) {
    unsigned x1 = addimm<B0>(c1, one);
    unsigned x0 = addimm<A0>(x1, one);   // round-1 add folded with x0 init
    x1 = __funnelshift_l(x1, x1, 13); x1 ^= x0;
#define TFR(r) { x0 = addf(x1, x0, one); \
                 x1 = __funnelshift_l(x1, x1, (r)); x1 ^= x0; }
    TFR(15) TFR(26) TFR(6)
    x0 = addimm<A1>(x0, one); x1 = addimm<B1>(x1, one);
    TFR(17) TFR(29) TFR(16) TFR(24)
    x0 = addimm<A2>(x0, one); x1 = addimm<B2>(x1, one);
    TFR(13) TFR(15) TFR(26) TFR(6)
    x0 = addimm<A3>(x0, one); x1 = addimm<B3>(x1, one);
    TFR(17) TFR(29) TFR(16) TFR(24)
    x0 = addimm<A4>(x0, one); x1 = addimm<B4>(x1, one);
    TFR(13) TFR(15) TFR(26) TFR(6)
    x0 = addimm<A5>(x0, one); x1 = addimm<B5>(x1, one);
#undef TFR
    return x0 ^ x1;
}

template<int T>
__device__ __forceinline__ void tf_bits4(unsigned bits[EPT], unsigned j,
                                         unsigned one) {
    constexpr Keys K = make_keys(T);
#pragma unroll
    for (int e = 0; e < EPT; e++) {
        bits[e] = tf_bits<K.a0,K.b0,K.a1,K.b1,K.a2,K.b2,
                          K.a3,K.b3,K.a4,K.b4,K.a5,K.b5>(j + (unsigned)e, one);
    }
}

// ---------------------------------------------------------------------------
// Predicated Bernoulli tail (one clamp per path; invariants make the other a
// no-op). Equivalent to: sp=u<p; oval=sp?ov1:ov0; rem=min(max(rem-sp,0),SM1).
// ---------------------------------------------------------------------------
__device__ __forceinline__ float bern_tail(float& rem, float u, float p,
                                           float ov0, float ov1, float sm1) {
    float oval;
    asm("{\n\t"
        ".reg .pred sp;\n\t"
        "setp.lt.f32 sp, %2, %3;\n\t"
        "selp.f32 %0, %4, %5, sp;\n\t"
        "@sp  add.f32 %1, %1, 0fBF800000;\n\t"   // rem -= 1
        "@sp  max.f32 %1, %1, 0f00000000;\n\t"   // clip low
        "@!sp min.f32 %1, %1, %6;\n\t"           // clip high
        "}"
        : "=f"(oval), "+f"(rem)
        : "f"(u), "f"(p), "f"(ov1), "f"(ov0), "f"(sm1));
    return oval;
}

// ---------------------------------------------------------------------------
// Float tail + store for one step, given precomputed random bits.
// ---------------------------------------------------------------------------
template<int T>
__device__ __forceinline__ void step_tail(const unsigned bits[EPT],
                                          float rem[EPT], unsigned j,
                                          float ov0, float ov1, unsigned c23,
                                          float* __restrict__ out)
{
    constexpr int   S    = TSTEPS - T;            // remaining slots
    constexpr float SF   = (float)S;
    constexpr float INV  = 1.0f / SF;             // rn(1/S), exact for pow2
    constexpr float SM1  = SF - 1.0f;
    constexpr bool  POW2 = (S & (S - 1)) == 0;

    float ovals[EPT];
#pragma unroll
    for (int e = 0; e < EPT; e++) {
        // u = bitcast((bits>>9)|0x3f800000) - 1.0 (exact Sterbenz subtraction)
        const float u = __uint_as_float(ubits(bits[e], c23)) - 1.0f;

        // p = rn(rem/S). Reference's clip(p,0,1) is a no-op (rem in [0,S]).
        float p;
        if (S == 1) {
            p = rem[e];
        } else if (POW2) {
            p = __fmul_rn(rem[e], INV);
        } else {
            const float q0 = __fmul_rn(rem[e], INV);
            const float r  = __fmaf_rn(-SF, q0, rem[e]);
            p = __fmaf_rn(r, INV, q0);            // Markstein, correctly rounded
        }

        if (S > 1) {
            ovals[e] = bern_tail(rem[e], u, p, ov0, ov1, SM1);
        } else {
            ovals[e] = (u < p) ? ov1 : ov0;       // last step: rem is dead
        }
    }

    float4 o;
    o.x = ovals[0]; o.y = ovals[1]; o.z = ovals[2]; o.w = ovals[3];
    // Streaming store: output is write-once, never re-read.
    __stcs(reinterpret_cast<float4*>(out + (size_t)T * NELEM + j), o);
}

template<int T>
__device__ __forceinline__ void do_step(float rem[EPT], unsigned j,
                                        float ov0, float ov1,
                                        unsigned one, unsigned c23,
                                        float* __restrict__ out)
{
    unsigned bits[EPT];
    tf_bits4<T>(bits, j, one);
    step_tail<T>(bits, rem, j, ov0, ov1, c23, out);
}

// ---------------------------------------------------------------------------
// Main kernel. __launch_bounds__(256, 4): 64+ reg budget (proven equal-best).
// Latency-hoisting: the x/mean/std loads are issued first, then the threefry
// blocks for steps 0 and 1 (~166 load-independent insts) execute WHILE the
// loads and the fdiv chains are in flight; the float tails consume xv only
// after that. This covers the per-CTA-start DRAM+MUFU latency that showed up
// as ~15% all-warps-stalled cycles in R8's profile.
// Grid covers NELEM exactly, so no bounds guard.
// ---------------------------------------------------------------------------
__global__ void __launch_bounds__(256, 4)
hyper_kernel(const float* __restrict__ x,
             const float* __restrict__ meanv,
             const float* __restrict__ stdv,
             float* __restrict__ out,
             unsigned one, unsigned c23)
{
    const unsigned j = (blockIdx.x * blockDim.x + threadIdx.x) * EPT;

    // Issue all loads up front.
    const float4 xv = *reinterpret_cast<const float4*>(x + j);
    const unsigned c = (j / HWPLANE) % 3u;
    const float m = meanv[c];
    const float s = stdv[c];

    // Load-independent work: threefry bits for steps 0 and 1.
    unsigned bits0[EPT], bits1[EPT];
    tf_bits4<0>(bits0, j, one);
    tf_bits4<1>(bits1, j, one);

    // Output values for spike=0 and spike=1: (spike - m) / s, IEEE divide.
    const float ov0 = __fdiv_rn(0.0f - m, s);
    const float ov1 = __fdiv_rn(1.0f - m, s);

    // probs = clip(x*s + m, 0, 1) (separate rn mul + rn add, matching XLA);
    // rem0 = probs * 16 (exact).
    float rem[EPT];
    {
        const float xs[EPT] = {xv.x, xv.y, xv.z, xv.w};
#pragma unroll
        for (int e = 0; e < EPT; e++) {
            float pr = __fadd_rn(__fmul_rn(xs[e], s), m);
            pr = fminf(fmaxf(pr, 0.0f), 1.0f);
            rem[e] = __fmul_rn(pr, 16.0f);
        }
    }

    step_tail<0>(bits0, rem, j, ov0, ov1, c23, out);
    step_tail<1>(bits1, rem, j, ov0, ov1, c23, out);
    do_step< 2>(rem, j, ov0, ov1, one, c23, out);
    do_step< 3>(rem, j, ov0, ov1, one, c23, out);
    do_step< 4>(rem, j, ov0, ov1, one, c23, out);
    do_step< 5>(rem, j, ov0, ov1, one, c23, out);
    do_step< 6>(rem, j, ov0, ov1, one, c23, out);
    do_step< 7>(rem, j, ov0, ov1, one, c23, out);
    do_step< 8>(rem, j, ov0, ov1, one, c23, out);
    do_step< 9>(rem, j, ov0, ov1, one, c23, out);
    do_step<10>(rem, j, ov0, ov1, one, c23, out);
    do_step<11>(rem, j, ov0, ov1, one, c23, out);
    do_step<12>(rem, j, ov0, ov1, one, c23, out);
    do_step<13>(rem, j, ov0, ov1, one, c23, out);
    do_step<14>(rem, j, ov0, ov1, one, c23, out);
    do_step<15>(rem, j, ov0, ov1, one, c23, out);
}

// ---------------------------------------------------------------------------
// Launch: single kernel, graph-capturable, allocation-free. The opaque
// 'one'/'c23' params keep the IMAD forms alive through ptxas.
// ---------------------------------------------------------------------------
extern "C" void kernel_launch(void* const* d_in, const int* in_sizes, int n_in,
                              void* d_out, int out_size) {
    (void)in_sizes; (void)n_in; (void)out_size;

    const float* x  = (const float*)d_in[0];
    const float* mn = (const float*)d_in[1];
    const float* sd = (const float*)d_in[2];
    float* out = (float*)d_out;

    const int threads = 256;
    const int blocks = NELEM / (threads * EPT);   // 9408 exactly
    hyper_kernel<<<blocks, threads>>>(x, mn, sd, out, 1u, 1u << 23);
}

// round 12
// speedup vs baseline: 1.2709x; 1.0007x over previous
#include <cuda_runtime.h>
#include <cstdint>

// Problem constants: x is [64,3,224,224] f32, out is [16,64,3,224,224] f32.
#define NELEM    9633792      // 64*3*224*224
#define HWPLANE  50176        // 224*224
#define TSTEPS   16
#define EPT      4            // elements per thread (float4 granularity)

// ---------------------------------------------------------------------------
// Compile-time key schedule: keys[t] = threefry2x32((0,1), (0,t)) under the
// partitionable split, with the 6 key-injection constants pre-folded.
// ---------------------------------------------------------------------------
struct Keys { unsigned a0,b0,a1,b1,a2,b2,a3,b3,a4,b4,a5,b5; };

__host__ __device__ constexpr unsigned rotlc(unsigned v, int r) {
    return (v << r) | (v >> (32 - r));
}

__host__ __device__ constexpr Keys make_keys(int t) {
    const unsigned k0 = 0u, k1 = 1u;
    const unsigned k2 = k0 ^ k1 ^ 0x1BD11BDAu;
    unsigned x0 = k0;                 // c0 = 0
    unsigned x1 = (unsigned)t + k1;   // c1 = t
    x0+=x1; x1=rotlc(x1,13); x1^=x0;
    x0+=x1; x1=rotlc(x1,15); x1^=x0;
    x0+=x1; x1=rotlc(x1,26); x1^=x0;
    x0+=x1; x1=rotlc(x1, 6); x1^=x0;
    x0+=k1; x1+=k2+1u;
    x0+=x1; x1=rotlc(x1,17); x1^=x0;
    x0+=x1; x1=rotlc(x1,29); x1^=x0;
    x0+=x1; x1=rotlc(x1,16); x1^=x0;
    x0+=x1; x1=rotlc(x1,24); x1^=x0;
    x0+=k2; x1+=k0+2u;
    x0+=x1; x1=rotlc(x1,13); x1^=x0;
    x0+=x1; x1=rotlc(x1,15); x1^=x0;
    x0+=x1; x1=rotlc(x1,26); x1^=x0;
    x0+=x1; x1=rotlc(x1, 6); x1^=x0;
    x0+=k0; x1+=k1+3u;
    x0+=x1; x1=rotlc(x1,17); x1^=x0;
    x0+=x1; x1=rotlc(x1,29); x1^=x0;
    x0+=x1; x1=rotlc(x1,16); x1^=x0;
    x0+=x1; x1=rotlc(x1,24); x1^=x0;
    x0+=k1; x1+=k2+4u;
    x0+=x1; x1=rotlc(x1,13); x1^=x0;
    x0+=x1; x1=rotlc(x1,15); x1^=x0;
    x0+=x1; x1=rotlc(x1,26); x1^=x0;
    x0+=x1; x1=rotlc(x1, 6); x1^=x0;
    x0+=k2; x1+=k0+5u;
    const unsigned K0 = x0, K1 = x1, K2 = K0 ^ K1 ^ 0x1BD11BDAu;
    return Keys{K0,K1, K1,K2+1u, K2,K0+2u, K0,K1+3u, K1,K2+4u, K2,K0+5u};
}

// ---------------------------------------------------------------------------
// FMA-pipe integer adds. 'one' (==1) comes from a kernel parameter, so ptxas
// cannot strength-reduce the IMAD forms back to IADD3.
// ---------------------------------------------------------------------------
__device__ __forceinline__ unsigned addf(unsigned a, unsigned b, unsigned one) {
    unsigned d;
    asm("mad.lo.u32 %0, %1, %2, %3;" : "=r"(d) : "r"(a), "r"(one), "r"(b));
    return d;
}

template<unsigned IMM>
__device__ __forceinline__ unsigned addimm(unsigned x, unsigned one) {
    unsigned d;
    asm("mad.lo.u32 %0, %1, %2, %3;" : "=r"(d) : "r"(one), "n"(IMM), "r"(x));
    return d;
}

// (bits >> 9) | 0x3f800000 as one op: hi32(bits * 2^23) + 0x3f800000
// (disjoint bit ranges, so OR == ADD). fma pipe (has headroom).
__device__ __forceinline__ unsigned ubits(unsigned bits, unsigned c23) {
    unsigned d;
    asm("mad.hi.u32 %0, %1, %2, %3;" : "=r"(d) : "r"(bits), "r"(c23),
        "n"(0x3f800000));
    return d;
}

// ---------------------------------------------------------------------------
// threefry2x32 (JAX-exact 20 rounds) with all key material as immediates.
// Returns o0 ^ o1 (partitionable bits fold).
// ---------------------------------------------------------------------------
template<unsigned A0,unsigned B0,unsigned A1,unsigned B1,unsigned A2,unsigned B2,
         unsigned A3,unsigned B3,unsigned A4,unsigned B4,unsigned A5,unsigned B5>
__device__ __forceinline__ unsigned tf_bits(unsigned c1, unsigned one) {
    unsigned x1 = addimm<B0>(c1, one);
    unsigned x0 = addimm<A0>(x1, one);   // round-1 add folded with x0 init
    x1 = __funnelshift_l(x1, x1, 13); x1 ^= x0;
#define TFR(r) { x0 = addf(x1, x0, one); \
                 x1 = __funnelshift_l(x1, x1, (r)); x1 ^= x0; }
    TFR(15) TFR(26) TFR(6)
    x0 = addimm<A1>(x0, one); x1 = addimm<B1>(x1, one);
    TFR(17) TFR(29) TFR(16) TFR(24)
    x0 = addimm<A2>(x0, one); x1 = addimm<B2>(x1, one);
    TFR(13) TFR(15) TFR(26) TFR(6)
    x0 = addimm<A3>(x0, one); x1 = addimm<B3>(x1, one);
    TFR(17) TFR(29) TFR(16) TFR(24)
    x0 = addimm<A4>(x0, one); x1 = addimm<B4>(x1, one);
    TFR(13) TFR(15) TFR(26) TFR(6)
    x0 = addimm<A5>(x0, one); x1 = addimm<B5>(x1, one);
#undef TFR
    return x0 ^ x1;
}

// ---------------------------------------------------------------------------
// Clampless mask-based Bernoulli tail.
// mask = (u < p) ? 0xFFFFFFFF : 0
// oval = bitselect(ov1, ov0, mask)            (one LOP3, lut 0xE2)
// spikef = uint_as_float(mask & 0x3f800000)   (1.0f or 0.0f, one AND)
// rem -= spikef                               (exact; fma pipe)
// The reference's clip(rem-spike, 0, slots-1) is dropped: decision-
// equivalence of the unclamped trajectory is proved in the round notes
// (overflow path forces spikes on both trajectories; underflow path
// forces no-spikes on both; otherwise trajectories are identical).
// ---------------------------------------------------------------------------
__device__ __forceinline__ float bern_tail(float& rem, float u, float p,
                                           float ov0, float ov1) {
    unsigned mask, ovalb, spikeb;
    asm("set.lt.u32.f32 %0, %1, %2;" : "=r"(mask) : "f"(u), "f"(p));
    asm("lop3.b32 %0, %1, %2, %3, 0xE2;" : "=r"(ovalb)
        : "r"(__float_as_uint(ov1)), "r"(mask), "r"(__float_as_uint(ov0)));
    asm("and.b32 %0, %1, 0x3f800000;" : "=r"(spikeb) : "r"(mask));
    rem = __fadd_rn(rem, -__uint_as_float(spikeb));   // rem -= {0,1}, exact
    return __uint_as_float(ovalb);
}

// Last step: rem is dead, just select the output value.
__device__ __forceinline__ float bern_last(float u, float p,
                                           float ov0, float ov1) {
    unsigned mask, ovalb;
    asm("set.lt.u32.f32 %0, %1, %2;" : "=r"(mask) : "f"(u), "f"(p));
    asm("lop3.b32 %0, %1, %2, %3, 0xE2;" : "=r"(ovalb)
        : "r"(__float_as_uint(ov1)), "r"(mask), "r"(__float_as_uint(ov0)));
    return __uint_as_float(ovalb);
}

// ---------------------------------------------------------------------------
// One fully specialized time step for 4 elements. The 4 threefry blocks are
// computed first (independent chains), then the float tail.
// ---------------------------------------------------------------------------
template<int T>
__device__ __forceinline__ void do_step(float rem[EPT], unsigned j,
                                        float ov0, float ov1,
                                        unsigned one, unsigned c23,
                                        float* __restrict__ out)
{
    constexpr int   S    = TSTEPS - T;            // remaining slots
    constexpr float SF   = (float)S;
    constexpr float INV  = 1.0f / SF;             // rn(1/S), exact for pow2
    constexpr bool  POW2 = (S & (S - 1)) == 0;
    constexpr Keys  K    = make_keys(T);

    unsigned bits[EPT];
#pragma unroll
    for (int e = 0; e < EPT; e++) {
        bits[e] = tf_bits<K.a0,K.b0,K.a1,K.b1,K.a2,K.b2,
                          K.a3,K.b3,K.a4,K.b4,K.a5,K.b5>(j + (unsigned)e, one);
    }

    float ovals[EPT];
#pragma unroll
    for (int e = 0; e < EPT; e++) {
        // u = bitcast((bits>>9)|0x3f800000) - 1.0 (exact Sterbenz subtraction)
        const float u = __uint_as_float(ubits(bits[e], c23)) - 1.0f;

        // p = rn(rem/S). Reference's clip(p,0,1) drops out: in-sync states
        // have rem in [0,S] (p in [0,1]); divergent states only need the
        // sign/>=1 behavior of p, which survives un-clipped (see notes).
        float p;
        if (S == 1) {
            p = rem[e];
        } else if (POW2) {
            p = __fmul_rn(rem[e], INV);
        } else {
            const float q0 = __fmul_rn(rem[e], INV);
            const float r  = __fmaf_rn(-SF, q0, rem[e]);
            p = __fmaf_rn(r, INV, q0);            // Markstein, correctly rounded
        }

        if (S > 1) {
            ovals[e] = bern_tail(rem[e], u, p, ov0, ov1);
        } else {
            ovals[e] = bern_last(u, p, ov0, ov1);
        }
    }

    float4 o;
    o.x = ovals[0]; o.y = ovals[1]; o.z = ovals[2]; o.w = ovals[3];
    // Streaming store: output is write-once, never re-read.
    __stcs(reinterpret_cast<float4*>(out + (size_t)T * NELEM + j), o);
}

// ---------------------------------------------------------------------------
// Main kernel. __launch_bounds__(256, 4): 64-reg budget (proven equal-best).
// Grid covers NELEM exactly, so no bounds guard. (R8 ordering: the R10
// hoist experiment was neutral, reverted.)
// ---------------------------------------------------------------------------
__global__ void __launch_bounds__(256, 4)
hyper_kernel(const float* __restrict__ x,
             const float* __restrict__ meanv,
             const float* __restrict__ stdv,
             float* __restrict__ out,
             unsigned one, unsigned c23)
{
    const unsigned j = (blockIdx.x * blockDim.x + threadIdx.x) * EPT;

    const unsigned c = (j / HWPLANE) % 3u;
    const float m = meanv[c];
    const float s = stdv[c];
    // Output values for spike=0 and spike=1: (spike - m) / s, IEEE divide.
    const float ov0 = __fdiv_rn(0.0f - m, s);
    const float ov1 = __fdiv_rn(1.0f - m, s);

    const float4 xv = *reinterpret_cast<const float4*>(x + j);

    // probs = clip(x*s + m, 0, 1) (separate rn mul + rn add, matching XLA);
    // rem0 = probs * 16 (exact).
    float rem[EPT];
    {
        const float xs[EPT] = {xv.x, xv.y, xv.z, xv.w};
#pragma unroll
        for (int e = 0; e < EPT; e++) {
            float pr = __fadd_rn(__fmul_rn(xs[e], s), m);
            pr = fminf(fmaxf(pr, 0.0f), 1.0f);
            rem[e] = __fmul_rn(pr, 16.0f);
        }
    }

    do_step< 0>(rem, j, ov0, ov1, one, c23, out);
    do_step< 1>(rem, j, ov0, ov1, one, c23, out);
    do_step< 2>(rem, j, ov0, ov1, one, c23, out);
    do_step< 3>(rem, j, ov0, ov1, one, c23, out);
    do_step< 4>(rem, j, ov0, ov1, one, c23, out);
    do_step< 5>(rem, j, ov0, ov1, one, c23, out);
    do_step< 6>(rem, j, ov0, ov1, one, c23, out);
    do_step< 7>(rem, j, ov0, ov1, one, c23, out);
    do_step< 8>(rem, j, ov0, ov1, one, c23, out);
    do_step< 9>(rem, j, ov0, ov1, one, c23, out);
    do_step<10>(rem, j, ov0, ov1, one, c23, out);
    do_step<11>(rem, j, ov0, ov1, one, c23, out);
    do_step<12>(rem, j, ov0, ov1, one, c23, out);
    do_step<13>(rem, j, ov0, ov1, one, c23, out);
    do_step<14>(rem, j, ov0, ov1, one, c23, out);
    do_step<15>(rem, j, ov0, ov1, one, c23, out);
}

// ---------------------------------------------------------------------------
// Launch: single kernel, graph-capturable, allocation-free. The opaque
// 'one'/'c23' params keep the IMAD forms alive through ptxas.
// ---------------------------------------------------------------------------
extern "C" void kernel_launch(void* const* d_in, const int* in_sizes, int n_in,
                              void* d_out, int out_size) {
    (void)in_sizes; (void)n_in; (void)out_size;

    const float* x  = (const float*)d_in[0];
    const float* mn = (const float*)d_in[1];
    const float* sd = (const float*)d_in[2];
    float* out = (float*)d_out;

    const int threads = 256;
    const int blocks = NELEM / (threads * EPT);   // 9408 exactly
    hyper_kernel<<<blocks, threads>>>(x, mn, sd, out, 1u, 1u << 23);
}

// round 13
// speedup vs baseline: 1.3065x; 1.0280x over previous
#include <cuda_runtime.h>
#include <cstdint>

// Problem constants: x is [64,3,224,224] f32, out is [16,64,3,224,224] f32.
#define NELEM    9633792      // 64*3*224*224
#define HWPLANE  50176        // 224*224
#define TSTEPS   16
#define EPT      4            // elements per thread (float4 granularity)

// ---------------------------------------------------------------------------
// Compile-time key schedule: keys[t] = threefry2x32((0,1), (0,t)) under the
// partitionable split, with the 6 key-injection constants pre-folded.
// ---------------------------------------------------------------------------
struct Keys { unsigned a0,b0,a1,b1,a2,b2,a3,b3,a4,b4,a5,b5; };

__host__ __device__ constexpr unsigned rotlc(unsigned v, int r) {
    return (v << r) | (v >> (32 - r));
}

__host__ __device__ constexpr Keys make_keys(int t) {
    const unsigned k0 = 0u, k1 = 1u;
    const unsigned k2 = k0 ^ k1 ^ 0x1BD11BDAu;
    unsigned x0 = k0;                 // c0 = 0
    unsigned x1 = (unsigned)t + k1;   // c1 = t
    x0+=x1; x1=rotlc(x1,13); x1^=x0;
    x0+=x1; x1=rotlc(x1,15); x1^=x0;
    x0+=x1; x1=rotlc(x1,26); x1^=x0;
    x0+=x1; x1=rotlc(x1, 6); x1^=x0;
    x0+=k1; x1+=k2+1u;
    x0+=x1; x1=rotlc(x1,17); x1^=x0;
    x0+=x1; x1=rotlc(x1,29); x1^=x0;
    x0+=x1; x1=rotlc(x1,16); x1^=x0;
    x0+=x1; x1=rotlc(x1,24); x1^=x0;
    x0+=k2; x1+=k0+2u;
    x0+=x1; x1=rotlc(x1,13); x1^=x0;
    x0+=x1; x1=rotlc(x1,15); x1^=x0;
    x0+=x1; x1=rotlc(x1,26); x1^=x0;
    x0+=x1; x1=rotlc(x1, 6); x1^=x0;
    x0+=k0; x1+=k1+3u;
    x0+=x1; x1=rotlc(x1,17); x1^=x0;
    x0+=x1; x1=rotlc(x1,29); x1^=x0;
    x0+=x1; x1=rotlc(x1,16); x1^=x0;
    x0+=x1; x1=rotlc(x1,24); x1^=x0;
    x0+=k1; x1+=k2+4u;
    x0+=x1; x1=rotlc(x1,13); x1^=x0;
    x0+=x1; x1=rotlc(x1,15); x1^=x0;
    x0+=x1; x1=rotlc(x1,26); x1^=x0;
    x0+=x1; x1=rotlc(x1, 6); x1^=x0;
    x0+=k2; x1+=k0+5u;
    const unsigned K0 = x0, K1 = x1, K2 = K0 ^ K1 ^ 0x1BD11BDAu;
    return Keys{K0,K1, K1,K2+1u, K2,K0+2u, K0,K1+3u, K1,K2+4u, K2,K0+5u};
}

// ---------------------------------------------------------------------------
// FMA-pipe integer adds. 'one' (==1) comes from a kernel parameter, so ptxas
// cannot strength-reduce the IMAD forms back to IADD3.
// ---------------------------------------------------------------------------
__device__ __forceinline__ unsigned addf(unsigned a, unsigned b, unsigned one) {
    unsigned d;
    asm("mad.lo.u32 %0, %1, %2, %3;" : "=r"(d) : "r"(a), "r"(one), "r"(b));
    return d;
}

template<unsigned IMM>
__device__ __forceinline__ unsigned addimm(unsigned x, unsigned one) {
    unsigned d;
    asm("mad.lo.u32 %0, %1, %2, %3;" : "=r"(d) : "r"(one), "n"(IMM), "r"(x));
    return d;
}

// (bits >> 9) | 0x3f800000 as one op: hi32(bits * 2^23) + 0x3f800000
// (disjoint bit ranges, so OR == ADD). fma pipe (has headroom).
__device__ __forceinline__ unsigned ubits(unsigned bits, unsigned c23) {
    unsigned d;
    asm("mad.hi.u32 %0, %1, %2, %3;" : "=r"(d) : "r"(bits), "r"(c23),
        "n"(0x3f800000));
    return d;
}

// ---------------------------------------------------------------------------
// threefry2x32 (JAX-exact 20 rounds) with all key material as immediates.
// Returns o0 ^ o1 (partitionable bits fold).
// ---------------------------------------------------------------------------
template<unsigned A0,unsigned B0,unsigned A1,unsigned B1,unsigned A2,unsigned B2,
         unsigned A3,unsigned B3,unsigned A4,unsigned B4,unsigned A5,unsigned B5>
__device__ __forceinline__ unsigned tf_bits(unsigned c1, unsigned one) {
    unsigned x1 = addimm<B0>(c1, one);
    unsigned x0 = addimm<A0>(x1, one);   // round-1 add folded with x0 init
    x1 = __funnelshift_l(x1, x1, 13); x1 ^= x0;
#define TFR(r) { x0 = addf(x1, x0, one); \
                 x1 = __funnelshift_l(x1, x1, (r)); x1 ^= x0; }
    TFR(15) TFR(26) TFR(6)
    x0 = addimm<A1>(x0, one); x1 = addimm<B1>(x1, one);
    TFR(17) TFR(29) TFR(16) TFR(24)
    x0 = addimm<A2>(x0, one); x1 = addimm<B2>(x1, one);
    TFR(13) TFR(15) TFR(26) TFR(6)
    x0 = addimm<A3>(x0, one); x1 = addimm<B3>(x1, one);
    TFR(17) TFR(29) TFR(16) TFR(24)
    x0 = addimm<A4>(x0, one); x1 = addimm<B4>(x1, one);
    TFR(13) TFR(15) TFR(26) TFR(6)
    x0 = addimm<A5>(x0, one); x1 = addimm<B5>(x1, one);
#undef TFR
    return x0 ^ x1;
}

// ---------------------------------------------------------------------------
// Clampless predicated Bernoulli tail (best of R8 + R12):
//   setp.lt sp, u, p      — spike decision
//   selp    oval          — output value select (R8 idiom, fastest measured)
//   @sp add rem, rem, -1  — unclamped rem update
// The reference's clip(rem-spike, 0, slots-1) is dropped: R12 executed the
// unclamped trajectory over the full dataset with rel_err == 0.0, validating
// the decision-equivalence proof (overflow divergence forces spikes on both
// trajectories since u < 1 <= p; underflow divergence forces no-spikes on
// both since p <= 0 <= u).
// ---------------------------------------------------------------------------
__device__ __forceinline__ float bern_tail(float& rem, float u, float p,
                                           float ov0, float ov1) {
    float oval;
    asm("{\n\t"
        ".reg .pred sp;\n\t"
        "setp.lt.f32 sp, %2, %3;\n\t"
        "selp.f32 %0, %4, %5, sp;\n\t"
        "@sp add.f32 %1, %1, 0fBF800000;\n\t"    // rem -= 1 (exact)
        "}"
        : "=f"(oval), "+f"(rem)
        : "f"(u), "f"(p), "f"(ov1), "f"(ov0));
    return oval;
}

// ---------------------------------------------------------------------------
// One fully specialized time step for 4 elements. The 4 threefry blocks are
// computed first (independent chains), then the float tail.
// ---------------------------------------------------------------------------
template<int T>
__device__ __forceinline__ void do_step(float rem[EPT], unsigned j,
                                        float ov0, float ov1,
                                        unsigned one, unsigned c23,
                                        float* __restrict__ out)
{
    constexpr int   S    = TSTEPS - T;            // remaining slots
    constexpr float SF   = (float)S;
    constexpr float INV  = 1.0f / SF;             // rn(1/S), exact for pow2
    constexpr bool  POW2 = (S & (S - 1)) == 0;
    constexpr Keys  K    = make_keys(T);

    unsigned bits[EPT];
#pragma unroll
    for (int e = 0; e < EPT; e++) {
        bits[e] = tf_bits<K.a0,K.b0,K.a1,K.b1,K.a2,K.b2,
                          K.a3,K.b3,K.a4,K.b4,K.a5,K.b5>(j + (unsigned)e, one);
    }

    float ovals[EPT];
#pragma unroll
    for (int e = 0; e < EPT; e++) {
        // u = bitcast((bits>>9)|0x3f800000) - 1.0 (exact Sterbenz subtraction)
        const float u = __uint_as_float(ubits(bits[e], c23)) - 1.0f;

        // p = rn(rem/S). Reference's clip(p,0,1) drops out: in-sync states
        // have rem in [0,S] (p in [0,1]); divergent states only need the
        // sign/>=1 behavior of p, which survives un-clipped (R12-validated).
        float p;
        if (S == 1) {
            p = rem[e];
        } else if (POW2) {
            p = __fmul_rn(rem[e], INV);
        } else {
            const float q0 = __fmul_rn(rem[e], INV);
            const float r  = __fmaf_rn(-SF, q0, rem[e]);
            p = __fmaf_rn(r, INV, q0);            // Markstein, correctly rounded
        }

        if (S > 1) {
            ovals[e] = bern_tail(rem[e], u, p, ov0, ov1);
        } else {
            ovals[e] = (u < p) ? ov1 : ov0;       // last step: rem is dead
        }
    }

    float4 o;
    o.x = ovals[0]; o.y = ovals[1]; o.z = ovals[2]; o.w = ovals[3];
    // Streaming store: output is write-once, never re-read.
    __stcs(reinterpret_cast<float4*>(out + (size_t)T * NELEM + j), o);
}

// ---------------------------------------------------------------------------
// Main kernel. __launch_bounds__(256, 4): 64-reg budget (proven equal-best).
// Grid covers NELEM exactly, so no bounds guard. R8 structure throughout.
// ---------------------------------------------------------------------------
__global__ void __launch_bounds__(256, 4)
hyper_kernel(const float* __restrict__ x,
             const float* __restrict__ meanv,
             const float* __restrict__ stdv,
             float* __restrict__ out,
             unsigned one, unsigned c23)
{
    const unsigned j = (blockIdx.x * blockDim.x + threadIdx.x) * EPT;

    const unsigned c = (j / HWPLANE) % 3u;
    const float m = meanv[c];
    const float s = stdv[c];
    // Output values for spike=0 and spike=1: (spike - m) / s, IEEE divide.
    const float ov0 = __fdiv_rn(0.0f - m, s);
    const float ov1 = __fdiv_rn(1.0f - m, s);

    const float4 xv = *reinterpret_cast<const float4*>(x + j);

    // probs = clip(x*s + m, 0, 1) (separate rn mul + rn add, matching XLA);
    // rem0 = probs * 16 (exact).
    float rem[EPT];
    {
        const float xs[EPT] = {xv.x, xv.y, xv.z, xv.w};
#pragma unroll
        for (int e = 0; e < EPT; e++) {
            float pr = __fadd_rn(__fmul_rn(xs[e], s), m);
            pr = fminf(fmaxf(pr, 0.0f), 1.0f);
            rem[e] = __fmul_rn(pr, 16.0f);
        }
    }

    do_step< 0>(rem, j, ov0, ov1, one, c23, out);
    do_step< 1>(rem, j, ov0, ov1, one, c23, out);
    do_step< 2>(rem, j, ov0, ov1, one, c23, out);
    do_step< 3>(rem, j, ov0, ov1, one, c23, out);
    do_step< 4>(rem, j, ov0, ov1, one, c23, out);
    do_step< 5>(rem, j, ov0, ov1, one, c23, out);
    do_step< 6>(rem, j, ov0, ov1, one, c23, out);
    do_step< 7>(rem, j, ov0, ov1, one, c23, out);
    do_step< 8>(rem, j, ov0, ov1, one, c23, out);
    do_step< 9>(rem, j, ov0, ov1, one, c23, out);
    do_step<10>(rem, j, ov0, ov1, one, c23, out);
    do_step<11>(rem, j, ov0, ov1, one, c23, out);
    do_step<12>(rem, j, ov0, ov1, one, c23, out);
    do_step<13>(rem, j, ov0, ov1, one, c23, out);
    do_step<14>(rem, j, ov0, ov1, one, c23, out);
    do_step<15>(rem, j, ov0, ov1, one, c23, out);
}

// ---------------------------------------------------------------------------
// Launch: single kernel, graph-capturable, allocation-free. The opaque
// 'one'/'c23' params keep the IMAD forms alive through ptxas.
// ---------------------------------------------------------------------------
extern "C" void kernel_launch(void* const* d_in, const int* in_sizes, int n_in,
                              void* d_out, int out_size) {
    (void)in_sizes; (void)n_in; (void)out_size;

    const float* x  = (const float*)d_in[0];
    const float* mn = (const float*)d_in[1];
    const float* sd = (const float*)d_in[2];
    float* out = (float*)d_out;

    const int threads = 256;
    const int blocks = NELEM / (threads * EPT);   // 9408 exactly
    hyper_kernel<<<blocks, threads>>>(x, mn, sd, out, 1u, 1u << 23);
}